// round 13
// baseline (speedup 1.0000x reference)
#include <cuda_runtime.h>
#include <cuda_bf16.h>
#include <math.h>

#define BB   8
#define N1   2048
#define N2   512
#define DD   128
#define KK   32
#define R3   27
#define NCH  81      // 3*27
#define FC   192

typedef unsigned long long ull;
typedef unsigned int uint;
typedef unsigned short ushort;

// ---- packed f32x2 helpers ----
__device__ __forceinline__ ull pack2(float x) {
    ull r; asm("mov.b64 %0, {%1, %1};" : "=l"(r) : "f"(x)); return r;
}
__device__ __forceinline__ void fma2(ull& d, ull a, ull b) {
    asm("fma.rn.f32x2 %0, %1, %2, %0;" : "+l"(d) : "l"(a), "l"(b));
}
__device__ __forceinline__ ull add2(ull a, ull b) {
    ull d; asm("add.rn.f32x2 %0, %1, %2;" : "=l"(d) : "l"(a), "l"(b)); return d;
}
__device__ __forceinline__ void unpack2(ull v, float& lo, float& hi) {
    asm("mov.b64 {%0, %1}, %2;" : "=f"(lo), "=f"(hi) : "l"(v));
}
__device__ __forceinline__ void split_bf16(float v, ushort& h, ushort& l) {
    ushort hb = __bfloat16_as_ushort(__float2bfloat16(v));
    float hf = __uint_as_float(((uint)hb) << 16);
    h = hb;
    l = __bfloat16_as_ushort(__float2bfloat16(v - hf));
}

#define MMA_BF16(D, A0, A1, A2, A3, B0, B1)                                   \
    asm volatile("mma.sync.aligned.m16n8k16.row.col.f32.bf16.bf16.f32 "       \
                 "{%0,%1,%2,%3}, {%4,%5,%6,%7}, {%8,%9}, {%0,%1,%2,%3};"      \
                 : "+f"((D)[0]), "+f"((D)[1]), "+f"((D)[2]), "+f"((D)[3])     \
                 : "r"(A0), "r"(A1), "r"(A2), "r"(A3), "r"(B0), "r"(B1))

// ---------------- scratch (device globals; no allocs allowed) ----------------
__device__ float  g_corr[BB * N1 * N2];          // 32 MB
__device__ ushort g_f1h[BB * N1 * DD];           // [b][n][d] bf16 hi (scaled)
__device__ ushort g_f1l[BB * N1 * DD];
__device__ ushort g_f2h[BB * N2 * DD];
__device__ ushort g_f2l[BB * N2 * DD];
__device__ float4 g_c2p[BB][N2];                 // padded coords2
__device__ float  g_vol [BB * N1 * NCH];         // [b][n][81]
__device__ float  g_h1  [BB * 128 * N1];         // [b][c][n]
__device__ float  g_hmm [BB * N1 * 128];         // [b][n][c: 0..63 max, 64..127 min]
__device__ float  g_W1T [NCH * 128];             // [q][c]
__device__ ushort g_hh[BB * N1 * FC];            // [b][n][192] H bf16 hi
__device__ ushort g_hl[BB * N1 * FC];
__device__ ushort g_wh[FC * FC];                 // [o][192] Wcat bf16 hi
__device__ ushort g_wl[FC * FC];
__device__ double g_volsum[BB][8][2];
__device__ double g_knnmom[BB][14];

// ---------------- prep: zero stats + W1T + Wcat split + coords2 pack ---------
__global__ __launch_bounds__(256) void prep_kernel(const float* __restrict__ W1,
                                                   const float* __restrict__ W2,
                                                   const float* __restrict__ Wo,
                                                   const float* __restrict__ c2) {
    int bid = blockIdx.x;
    int tid = threadIdx.x;
    if (bid < 41) {                                    // W1 transpose -> [q][c]
        int i = bid * 256 + tid;
        if (i < NCH * 128) {
            int q = i >> 7, c = i & 127;
            g_W1T[q * 128 + c] = W1[c * NCH + q];
        }
    } else if (bid < 185) {                            // Wcat split bf16 [o][192]
        int i = (bid - 41) * 256 + tid;
        int o = i / FC, k = i - o * FC;
        float v = (k < 128) ? W2[o * 128 + k] : Wo[o * 64 + (k - 128)];
        ushort h, l; split_bf16(v, h, l);
        g_wh[i] = h; g_wl[i] = l;
    } else if (bid == 185) {                           // zero stat accumulators
        double* vs = &g_volsum[0][0][0];
        double* km = &g_knnmom[0][0];
        if (tid < BB * 8 * 2) vs[tid] = 0.0;
        if (tid < BB * 14)    km[tid] = 0.0;
    } else {                                           // coords2 -> float4
        int b = bid - 186;
        for (int m = tid; m < N2; m += 256) {
            const float* p = c2 + ((size_t)b * N2 + m) * 3;
            g_c2p[b][m] = make_float4(p[0], p[1], p[2], 0.f);
        }
    }
}

// ---------------- fmaps fp32 -> split bf16, transposed [n][d] ----
__global__ __launch_bounds__(256) void cvt_kernel(const float* __restrict__ f1,
                                                  const float* __restrict__ f2) {
    int b = blockIdx.z;
    bool isA = blockIdx.x < 64;
    int ntile = isA ? blockIdx.x : blockIdx.x - 64;
    int dtile = blockIdx.y;
    int NN = isA ? N1 : N2;
    const float* src = isA ? f1 + (size_t)b * DD * N1 : f2 + (size_t)b * DD * N2;
    ushort* dh = isA ? g_f1h + (size_t)b * N1 * DD : g_f2h + (size_t)b * N2 * DD;
    ushort* dl = isA ? g_f1l + (size_t)b * N1 * DD : g_f2l + (size_t)b * N2 * DD;
    float scale = isA ? 0.08838834764831845f : 1.0f;

    __shared__ float tile[32][33];
    int tid = threadIdx.x;
    for (int i = tid; i < 1024; i += 256) {
        int dd = i >> 5, nn = i & 31;
        tile[dd][nn] = src[(size_t)(dtile * 32 + dd) * NN + ntile * 32 + nn];
    }
    __syncthreads();
    for (int i = tid; i < 1024; i += 256) {
        int nn = i >> 5, dd = i & 31;
        float v = tile[dd][nn] * scale;
        ushort hb, lb; split_bf16(v, hb, lb);
        size_t o = (size_t)(ntile * 32 + nn) * DD + dtile * 32 + dd;
        dh[o] = hb;
        dl[o] = lb;
    }
}

// ---------------- corr via split-bf16 mma.sync; tile 128(n1) x 64(n2) -------
#define CPITCH 40
__global__ __launch_bounds__(256) void corr_kernel() {
    int b  = blockIdx.z;
    int n0 = blockIdx.x * 128;
    int m0 = blockIdx.y * 64;
    __shared__ ushort Ah[128][CPITCH], Al[128][CPITCH];
    __shared__ ushort Bh[64][CPITCH], Bl[64][CPITCH];
    int tid = threadIdx.x, lane = tid & 31, warp = tid >> 5;
    int wm = warp >> 1, wn = warp & 1;   // 4(m) x 2(n) warps; warp tile 32x32
    int g = lane >> 2, t = lane & 3;

    const ushort* f1h = g_f1h + (size_t)b * N1 * DD;
    const ushort* f1l = g_f1l + (size_t)b * N1 * DD;
    const ushort* f2h = g_f2h + (size_t)b * N2 * DD;
    const ushort* f2l = g_f2l + (size_t)b * N2 * DD;

    float d[2][4][4];
#pragma unroll
    for (int i = 0; i < 2; i++)
#pragma unroll
        for (int j = 0; j < 4; j++)
#pragma unroll
            for (int k = 0; k < 4; k++) d[i][j][k] = 0.f;

    for (int kc = 0; kc < 4; kc++) {
        int k0 = kc * 32;
        for (int i = tid; i < 512; i += 256) {
            int r = i >> 2, jj = (i & 3) * 8;
            *(uint4*)&Ah[r][jj] = *(const uint4*)&f1h[(size_t)(n0 + r) * DD + k0 + jj];
            *(uint4*)&Al[r][jj] = *(const uint4*)&f1l[(size_t)(n0 + r) * DD + k0 + jj];
        }
        for (int i = tid; i < 256; i += 256) {
            int r = i >> 2, jj = (i & 3) * 8;
            *(uint4*)&Bh[r][jj] = *(const uint4*)&f2h[(size_t)(m0 + r) * DD + k0 + jj];
            *(uint4*)&Bl[r][jj] = *(const uint4*)&f2l[(size_t)(m0 + r) * DD + k0 + jj];
        }
        __syncthreads();

#pragma unroll
        for (int term = 0; term < 3; term++) {
            const ushort (*Ap)[CPITCH] = (term == 2) ? Al : Ah;
            const ushort (*Bp)[CPITCH] = (term == 1) ? Bl : Bh;
#pragma unroll
            for (int ks = 0; ks < 2; ks++) {
                int sc = 16 * ks + 2 * t;
                uint bf[4][2];
#pragma unroll
                for (int nt = 0; nt < 4; nt++) {
                    int br = wn * 32 + nt * 8 + g;
                    bf[nt][0] = *(const uint*)&Bp[br][sc];
                    bf[nt][1] = *(const uint*)&Bp[br][sc + 8];
                }
#pragma unroll
                for (int mt = 0; mt < 2; mt++) {
                    int ar = wm * 32 + mt * 16 + g;
                    uint a0 = *(const uint*)&Ap[ar][sc];
                    uint a1 = *(const uint*)&Ap[ar + 8][sc];
                    uint a2 = *(const uint*)&Ap[ar][sc + 8];
                    uint a3 = *(const uint*)&Ap[ar + 8][sc + 8];
#pragma unroll
                    for (int nt = 0; nt < 4; nt++)
                        MMA_BF16(d[mt][nt], a0, a1, a2, a3, bf[nt][0], bf[nt][1]);
                }
            }
        }
        __syncthreads();
    }

#pragma unroll
    for (int mt = 0; mt < 2; mt++) {
#pragma unroll
        for (int nt = 0; nt < 4; nt++) {
            int ng = n0 + wm * 32 + mt * 16 + g;
            int mg = m0 + wn * 32 + nt * 8 + 2 * t;
            float2 v0 = make_float2(d[mt][nt][0], d[mt][nt][1]);
            float2 v1 = make_float2(d[mt][nt][2], d[mt][nt][3]);
            *(float2*)&g_corr[((size_t)b * N1 + ng) * N2 + mg] = v0;
            *(float2*)&g_corr[((size_t)b * N1 + ng + 8) * N2 + mg] = v1;
        }
    }
}

// ---------------- row pass: voxel bins + KNN + e-moments + h minmax ---
__global__ __launch_bounds__(256) void row_kernel(const float* __restrict__ coords,
                           const float* __restrict__ Wk,
                           const float* __restrict__ bk) {
    int b    = blockIdx.y;
    int warp = threadIdx.x >> 5;
    int lane = threadIdx.x & 31;
    int n    = blockIdx.x * 8 + warp;

    __shared__ float4 s_c2[N2];            // overlaid by sev after last use
    __shared__ float sadd[8][NCH];
    __shared__ float scnt[8][NCH];
    __shared__ float smom[14];
    __shared__ float smm[8][128];
    float4* sev = s_c2;                    // [warp*32 + t], first 4 KB reused

    if (threadIdx.x < 14) smom[threadIdx.x] = 0.f;
    for (int q = lane; q < NCH; q += 32) { sadd[warp][q] = 0.f; scnt[warp][q] = 0.f; }
    for (int i = threadIdx.x; i < N2; i += 256)
        s_c2[i] = g_c2p[b][i];
    __syncthreads();

    float cx = coords[((size_t)b * N1 + n) * 3 + 0];
    float cy = coords[((size_t)b * N1 + n) * 3 + 1];
    float cz = coords[((size_t)b * N1 + n) * 3 + 2];
    const float* crow = g_corr + ((size_t)b * N1 + n) * N2;

    // ---- binning (nested level guards; bounds checks folded into mx tests)
    float dloc[16];
#pragma unroll 4
    for (int s = 0; s < 16; s++) {
        int m = lane + s * 32;
        float4 c = s_c2[m];
        float qx = c.x - cx;
        float qy = c.y - cy;
        float qz = c.z - cz;
        dloc[s] = qx * qx + qy * qy + qz * qz;
        float mx = fmaxf(fabsf(qx), fmaxf(fabsf(qy), fabsf(qz)));
        if (mx < 1.5f) {
            float cv = crow[m];
            int vx = __float2int_rn(qx);
            int vy = __float2int_rn(qy);
            int vz = __float2int_rn(qz);
            int idx = 54 + vx * 9 + vy * 3 + vz + 13;
            atomicAdd(&sadd[warp][idx], cv);
            atomicAdd(&scnt[warp][idx], 1.f);
            if (mx < 0.75f) {
                vx = __float2int_rn(qx * 2.f);
                vy = __float2int_rn(qy * 2.f);
                vz = __float2int_rn(qz * 2.f);
                idx = 27 + vx * 9 + vy * 3 + vz + 13;
                atomicAdd(&sadd[warp][idx], cv);
                atomicAdd(&scnt[warp][idx], 1.f);
                if (mx < 0.375f) {
                    vx = __float2int_rn(qx * 4.f);
                    vy = __float2int_rn(qy * 4.f);
                    vz = __float2int_rn(qz * 4.f);
                    idx = vx * 9 + vy * 3 + vz + 13;
                    atomicAdd(&sadd[warp][idx], cv);
                    atomicAdd(&scnt[warp][idx], 1.f);
                }
            }
        }
    }

    // ---- top-32 via 4-deep per-lane queue + branchless pop tournament ----
    unsigned consumed = 0;
    unsigned q0d, q0m, q1d, q1m, q2d, q2m, q3d, q3m;
    {
        float bv; int bs;
#define SCAN_MIN(OUTD, OUTM)                                            \
        bv = 3.4e38f; bs = 16;                                          \
        _Pragma("unroll")                                               \
        for (int s = 0; s < 16; s++) {                                  \
            bool ok = !((consumed >> s) & 1u) && (dloc[s] < bv);        \
            if (ok) { bv = dloc[s]; bs = s; }                           \
        }                                                               \
        OUTD = __float_as_uint(bv);                                     \
        OUTM = (unsigned)(lane + bs * 32);                              \
        consumed |= 1u << bs;
        SCAN_MIN(q0d, q0m)
        SCAN_MIN(q1d, q1m)
        SCAN_MIN(q2d, q2m)
        SCAN_MIN(q3d, q3m)
    }
    unsigned selm = 0;
    for (int k = 0; k < KK; k++) {
        unsigned dmin = __reduce_min_sync(0xffffffffu, q0d);
        unsigned mc   = (q0d == dmin) ? q0m : 0xffffffffu;
        unsigned mmin = __reduce_min_sync(0xffffffffu, mc);
        if (lane == k) selm = mmin;
        bool won = (q0d == dmin) && (q0m == mmin);
        q0d = won ? q1d : q0d;  q0m = won ? q1m : q0m;
        q1d = won ? q2d : q1d;  q1m = won ? q2m : q1m;
        q2d = won ? q3d : q2d;  q2m = won ? q3m : q2m;
        q3d = won ? 0xffffffffu : q3d;  q3m = won ? 0xffffffffu : q3m;
        if (__any_sync(0xffffffffu, (q0d == 0xffffffffu) & (consumed != 0xffffu))) {
            if ((q0d == 0xffffffffu) & (consumed != 0xffffu)) {
                float bv = 3.4e38f; int bs = 16;
#pragma unroll
                for (int s = 0; s < 16; s++) {
                    bool ok = !((consumed >> s) & 1u) && (dloc[s] < bv);
                    if (ok) { bv = dloc[s]; bs = s; }
                }
                if (bs < 16) {
                    q0d = __float_as_uint(bv);
                    q0m = (unsigned)(lane + bs * 32);
                    consumed |= 1u << bs;
                }
            }
        }
    }

    // ---- e vector for my selected neighbor (last s_c2 use) ----
    int j = (int)selm;
    float e0 = crow[j];
    float4 cj = s_c2[j];
    float e1 = cj.x - cx;
    float e2 = cj.y - cy;
    float e3 = cj.z - cz;

    // all warps done reading s_c2 -> safe to overlay sev into its storage
    __syncthreads();
    sev[warp * 32 + lane] = make_float4(e0, e1, e2, e3);

    float mv[14] = { e0, e1, e2, e3,
                     e0*e0, e0*e1, e0*e2, e0*e3,
                     e1*e1, e1*e2, e1*e3,
                     e2*e2, e2*e3, e3*e3 };
#pragma unroll
    for (int i = 0; i < 14; i++) {
        float v = mv[i];
#pragma unroll
        for (int off = 16; off; off >>= 1) v += __shfl_xor_sync(0xffffffffu, v, off);
        if (lane == 0) atomicAdd(&smom[i], v);
    }
    __syncwarp();

    // ---- per-channel max/min of raw h over 32 neighbors (smem broadcast) ----
    {
        float4 w0 = ((const float4*)Wk)[lane];
        float4 w1 = ((const float4*)Wk)[lane + 32];
        float bb0 = bk[lane], bb1 = bk[lane + 32];
        float mx0 = -3.4e38f, mn0 = 3.4e38f, mx1 = -3.4e38f, mn1 = 3.4e38f;
#pragma unroll 8
        for (int t = 0; t < 32; t++) {
            float4 e = sev[warp * 32 + t];
            float h0 = fmaf(w0.w, e.w, fmaf(w0.z, e.z, fmaf(w0.y, e.y, fmaf(w0.x, e.x, bb0))));
            float h1 = fmaf(w1.w, e.w, fmaf(w1.z, e.z, fmaf(w1.y, e.y, fmaf(w1.x, e.x, bb1))));
            mx0 = fmaxf(mx0, h0); mn0 = fminf(mn0, h0);
            mx1 = fmaxf(mx1, h1); mn1 = fminf(mn1, h1);
        }
        smm[warp][lane]           = mx0;
        smm[warp][lane + 32]      = mx1;
        smm[warp][64 + lane]      = mn0;
        smm[warp][64 + lane + 32] = mn1;
    }

    // voxel features (scatter mean), coalesced row layout [n][81]
    for (int q = lane; q < NCH; q += 32) {
        float cnt = scnt[warp][q];
        g_vol[((size_t)b * N1 + n) * NCH + q] = sadd[warp][q] / fmaxf(cnt, 1.f);
    }
    __syncthreads();
    if (threadIdx.x < 14) atomicAdd(&g_knnmom[b][threadIdx.x], (double)smom[threadIdx.x]);
    int nb = blockIdx.x * 8;
    for (int i = threadIdx.x; i < 8 * 128; i += 256) {
        int r = i >> 7;
        g_hmm[((size_t)b * N1 + nb + r) * 128 + (i & 127)] = smm[r][i & 127];
    }
}

// ---------------- h1 = W1 @ vol + b1, plus GN partial stats (FFMA2) ----------
__global__ __launch_bounds__(256) void h1_kernel(const float* __restrict__ b1) {
    int b  = blockIdx.y;
    int n0 = blockIdx.x * 64;
    int tx = threadIdx.x & 15;
    int ty = threadIdx.x >> 4;
    __shared__ float Ws[27][128];
    __shared__ float Vs[27][64];
    __shared__ float sgs[8], sgss[8];
    if (threadIdx.x < 8) { sgs[threadIdx.x] = 0.f; sgss[threadIdx.x] = 0.f; }

    ull acc2[8][2];
#pragma unroll
    for (int i = 0; i < 8; i++) { acc2[i][0] = 0ull; acc2[i][1] = 0ull; }

    for (int chunk = 0; chunk < 3; chunk++) {
        int q0 = chunk * 27;
        for (int i = threadIdx.x; i < 27 * 128; i += 256) {
            int q = i >> 7, c = i & 127;
            Ws[q][c] = g_W1T[(q0 + q) * 128 + c];
        }
        for (int i = threadIdx.x; i < 27 * 64; i += 256) {
            int nn = i / 27, q = i - nn * 27;
            Vs[q][nn] = g_vol[((size_t)b * N1 + n0 + nn) * NCH + q0 + q];
        }
        __syncthreads();
#pragma unroll
        for (int q = 0; q < 27; q++) {
            float4 a0 = *(const float4*)&Ws[q][ty * 8];
            float4 a1 = *(const float4*)&Ws[q][ty * 8 + 4];
            ulonglong2 bp = *(const ulonglong2*)&Vs[q][tx * 4];
            float av[8] = {a0.x, a0.y, a0.z, a0.w, a1.x, a1.y, a1.z, a1.w};
#pragma unroll
            for (int i = 0; i < 8; i++) {
                ull a2 = pack2(av[i]);
                fma2(acc2[i][0], a2, bp.x);
                fma2(acc2[i][1], a2, bp.y);
            }
        }
        __syncthreads();
    }

    float ls = 0.f, lss = 0.f;
#pragma unroll
    for (int i = 0; i < 8; i++) {
        int c = ty * 8 + i;
        ull b2v = pack2(b1[c]);
        ulonglong2 v;
        v.x = add2(acc2[i][0], b2v);
        v.y = add2(acc2[i][1], b2v);
        *(ulonglong2*)(g_h1 + ((size_t)b * 128 + c) * N1 + n0 + tx * 4) = v;
        float x0, x1, x2, x3;
        unpack2(v.x, x0, x1);
        unpack2(v.y, x2, x3);
        ls  += x0 + x1 + x2 + x3;
        lss += x0 * x0 + x1 * x1 + x2 * x2 + x3 * x3;
    }
    int g = ty >> 1;
    atomicAdd(&sgs[g], ls);
    atomicAdd(&sgss[g], lss);
    __syncthreads();
    if (threadIdx.x < 8) {
        atomicAdd(&g_volsum[b][threadIdx.x][0], (double)sgs[threadIdx.x]);
        atomicAdd(&g_volsum[b][threadIdx.x][1], (double)sgss[threadIdx.x]);
    }
}

// ---------------- hcvt: finalize stats in-block, then H -> bf16 split [n][192]
__global__ __launch_bounds__(256) void hcvt_kernel(const float* __restrict__ g1, const float* __restrict__ be1,
                                                   const float* __restrict__ a1p,
                                                   const float* __restrict__ gk, const float* __restrict__ bek,
                                                   const float* __restrict__ akp,
                                                   const float* __restrict__ Wk, const float* __restrict__ bk) {
    int b  = blockIdx.y;
    int n0 = blockIdx.x * 128;
    float a1 = a1p[0], ak = akp[0];
    __shared__ float sv[64][129];
    __shared__ float s_vstat[8][2];
    __shared__ float s_kstat[8][2];

    if (threadIdx.x < 8) {
        int g = threadIdx.x;
        double cnt = 16.0 * (double)N1;
        double mean = g_volsum[b][g][0] / cnt;
        double var = g_volsum[b][g][1] / cnt - mean * mean;
        s_vstat[g][0] = (float)mean;
        s_vstat[g][1] = (float)(1.0 / sqrt(var + 1e-5));
    } else if (threadIdx.x < 16) {
        int g = threadIdx.x - 8;
        double cnt = (double)N1 * (double)KK;
        double mu[4];
#pragma unroll
        for (int i = 0; i < 4; i++) mu[i] = g_knnmom[b][i] / cnt;
        double S[4][4];
        const int pi[10][2] = {{0,0},{0,1},{0,2},{0,3},{1,1},{1,2},{1,3},{2,2},{2,3},{3,3}};
#pragma unroll
        for (int p = 0; p < 10; p++) {
            double v = g_knnmom[b][4 + p] / cnt;
            S[pi[p][0]][pi[p][1]] = v;
            S[pi[p][1]][pi[p][0]] = v;
        }
        double sm = 0.0, s2 = 0.0;
        for (int c = g * 8; c < g * 8 + 8; c++) {
            double w[4] = { (double)Wk[c*4+0], (double)Wk[c*4+1], (double)Wk[c*4+2], (double)Wk[c*4+3] };
            double bb = (double)bk[c];
            double wm = w[0]*mu[0] + w[1]*mu[1] + w[2]*mu[2] + w[3]*mu[3];
            double q = 0.0;
#pragma unroll
            for (int i = 0; i < 4; i++)
#pragma unroll
                for (int jj = 0; jj < 4; jj++) q += w[i] * S[i][jj] * w[jj];
            double m1 = wm + bb;
            double m2 = q + 2.0 * bb * wm + bb * bb;
            sm += m1; s2 += m2;
        }
        sm *= 0.125; s2 *= 0.125;
        double var = s2 - sm * sm;
        s_kstat[g][0] = (float)sm;
        s_kstat[g][1] = (float)(1.0 / sqrt(var + 1e-5));
    }
    __syncthreads();

    for (int chunk = 0; chunk < 2; chunk++) {
        int c0 = chunk * 64;
        for (int i = threadIdx.x; i < 64 * 128; i += 256) {
            int c = i >> 7, nn = i & 127;
            int k = c0 + c, g = k >> 4;
            float v = g_h1[((size_t)b * 128 + k) * N1 + n0 + nn];
            v = (v - s_vstat[g][0]) * s_vstat[g][1];
            v = v * g1[k] + be1[k];
            sv[c][nn] = (v >= 0.f) ? v : a1 * v;
        }
        __syncthreads();
#pragma unroll
        for (int p = 0; p < 8; p++) {
            int nn = p * 16 + (threadIdx.x >> 4);
            int c4 = (threadIdx.x & 15) * 4;
            ushort4 hh, hl;
            split_bf16(sv[c4 + 0][nn], hh.x, hl.x);
            split_bf16(sv[c4 + 1][nn], hh.y, hl.y);
            split_bf16(sv[c4 + 2][nn], hh.z, hl.z);
            split_bf16(sv[c4 + 3][nn], hh.w, hl.w);
            size_t base = ((size_t)b * N1 + n0 + nn) * FC + c0 + c4;
            *(ushort4*)&g_hh[base] = hh;
            *(ushort4*)&g_hl[base] = hl;
        }
        __syncthreads();
    }
    for (int i = threadIdx.x; i < 128 * 64; i += 256) {
        int nn = i >> 6, c = i & 63;
        int g = c >> 3;
        float slope = s_kstat[g][1] * gk[c];
        const float* hm = g_hmm + ((size_t)b * N1 + n0 + nn) * 128;
        float hsel = (slope >= 0.f) ? hm[c] : hm[64 + c];
        float v = (hsel - s_kstat[g][0]) * slope + bek[c];
        v = (v >= 0.f) ? v : ak * v;
        ushort h, l; split_bf16(v, h, l);
        size_t base = ((size_t)b * N1 + nn + n0) * FC + 128 + c;
        g_hh[base] = h;
        g_hl[base] = l;
    }
}

// ---------------- outmma: out = Wcat @ H + (b2+bo), split-bf16 mma ----------
__global__ __launch_bounds__(256) void outmma_kernel(const float* __restrict__ b2,
                                                     const float* __restrict__ bo,
                                                     float* __restrict__ out) {
    int b  = blockIdx.z;
    int o0 = blockIdx.y * 64;
    int n0 = blockIdx.x * 128;
    __shared__ ushort Ah[64][CPITCH], Al[64][CPITCH];
    __shared__ ushort Bh[128][CPITCH], Bl[128][CPITCH];
    int tid = threadIdx.x, lane = tid & 31, warp = tid >> 5;
    int wm = warp >> 2, wn = warp & 3;
    int g = lane >> 2, t = lane & 3;

    float d[2][4][4];
#pragma unroll
    for (int i = 0; i < 2; i++)
#pragma unroll
        for (int j = 0; j < 4; j++)
#pragma unroll
            for (int k = 0; k < 4; k++) d[i][j][k] = 0.f;

    for (int kc = 0; kc < 6; kc++) {
        int k0 = kc * 32;
        for (int i = tid; i < 256; i += 256) {
            int r = i >> 2, jj = (i & 3) * 8;
            *(uint4*)&Ah[r][jj] = *(const uint4*)&g_wh[(o0 + r) * FC + k0 + jj];
            *(uint4*)&Al[r][jj] = *(const uint4*)&g_wl[(o0 + r) * FC + k0 + jj];
        }
        for (int i = tid; i < 512; i += 256) {
            int r = i >> 2, jj = (i & 3) * 8;
            *(uint4*)&Bh[r][jj] = *(const uint4*)&g_hh[((size_t)b * N1 + n0 + r) * FC + k0 + jj];
            *(uint4*)&Bl[r][jj] = *(const uint4*)&g_hl[((size_t)b * N1 + n0 + r) * FC + k0 + jj];
        }
        __syncthreads();

#pragma unroll
        for (int term = 0; term < 3; term++) {
            const ushort (*Ap)[CPITCH] = (term == 2) ? Al : Ah;
            const ushort (*Bp)[CPITCH] = (term == 1) ? Bl : Bh;
#pragma unroll
            for (int ks = 0; ks < 2; ks++) {
                int sc = 16 * ks + 2 * t;
                uint bf[4][2];
#pragma unroll
                for (int nt = 0; nt < 4; nt++) {
                    int br = wn * 32 + nt * 8 + g;
                    bf[nt][0] = *(const uint*)&Bp[br][sc];
                    bf[nt][1] = *(const uint*)&Bp[br][sc + 8];
                }
#pragma unroll
                for (int mt = 0; mt < 2; mt++) {
                    int ar = wm * 32 + mt * 16 + g;
                    uint a0 = *(const uint*)&Ap[ar][sc];
                    uint a1 = *(const uint*)&Ap[ar + 8][sc];
                    uint a2 = *(const uint*)&Ap[ar][sc + 8];
                    uint a3 = *(const uint*)&Ap[ar + 8][sc + 8];
#pragma unroll
                    for (int nt = 0; nt < 4; nt++)
                        MMA_BF16(d[mt][nt], a0, a1, a2, a3, bf[nt][0], bf[nt][1]);
                }
            }
        }
        __syncthreads();
    }

#pragma unroll
    for (int mt = 0; mt < 2; mt++) {
#pragma unroll
        for (int nt = 0; nt < 4; nt++) {
            int o = o0 + wm * 32 + mt * 16 + g;
            int n = n0 + wn * 32 + nt * 8 + 2 * t;
            float bias0 = b2[o] + bo[o];
            float bias1 = b2[o + 8] + bo[o + 8];
            float2 v0 = make_float2(d[mt][nt][0] + bias0, d[mt][nt][1] + bias0);
            float2 v1 = make_float2(d[mt][nt][2] + bias1, d[mt][nt][3] + bias1);
            *(float2*)&out[((size_t)b * FC + o) * N1 + n] = v0;
            *(float2*)&out[((size_t)b * FC + o + 8) * N1 + n] = v1;
        }
    }
}

// ---------------- launch ----------------
extern "C" void kernel_launch(void* const* d_in, const int* in_sizes, int n_in,
                              void* d_out, int out_size) {
    const float* coords  = (const float*)d_in[0];
    const float* coords2 = (const float*)d_in[1];
    const float* fmap1   = (const float*)d_in[2];
    const float* fmap2   = (const float*)d_in[3];
    const float* W1  = (const float*)d_in[4];
    const float* b1  = (const float*)d_in[5];
    const float* g1  = (const float*)d_in[6];
    const float* be1 = (const float*)d_in[7];
    const float* a1  = (const float*)d_in[8];
    const float* W2  = (const float*)d_in[9];
    const float* b2  = (const float*)d_in[10];
    const float* Wk  = (const float*)d_in[11];
    const float* bk  = (const float*)d_in[12];
    const float* gk  = (const float*)d_in[13];
    const float* bek = (const float*)d_in[14];
    const float* ak  = (const float*)d_in[15];
    const float* Wo  = (const float*)d_in[16];
    const float* bo  = (const float*)d_in[17];
    float* out = (float*)d_out;

    cvt_kernel<<<dim3(80, 4, BB), 256>>>(fmap1, fmap2);                // 0
    corr_kernel<<<dim3(N1 / 128, N2 / 64, BB), 256>>>();               // 1
    prep_kernel<<<194, 256>>>(W1, W2, Wo, coords2);                    // 2
    row_kernel<<<dim3(N1 / 8, BB), 256>>>(coords, Wk, bk);             // 3 (profiled slot)
    h1_kernel<<<dim3(N1 / 64, BB), 256>>>(b1);                         // 4
    hcvt_kernel<<<dim3(N1 / 128, BB), 256>>>(g1, be1, a1, gk, bek, ak, Wk, bk); // 5
    outmma_kernel<<<dim3(N1 / 128, FC / 64, BB), 256>>>(b2, bo, out);  // 6
}

// round 14
// speedup vs baseline: 1.0296x; 1.0296x over previous
#include <cuda_runtime.h>
#include <cuda_bf16.h>
#include <math.h>

#define BB   8
#define N1   2048
#define N2   512
#define DD   128
#define KK   32
#define R3   27
#define NCH  81      // 3*27
#define FC   192

typedef unsigned long long ull;
typedef unsigned int uint;
typedef unsigned short ushort;

// ---- packed f32x2 helpers ----
__device__ __forceinline__ ull pack2(float x) {
    ull r; asm("mov.b64 %0, {%1, %1};" : "=l"(r) : "f"(x)); return r;
}
__device__ __forceinline__ void fma2(ull& d, ull a, ull b) {
    asm("fma.rn.f32x2 %0, %1, %2, %0;" : "+l"(d) : "l"(a), "l"(b));
}
__device__ __forceinline__ ull add2(ull a, ull b) {
    ull d; asm("add.rn.f32x2 %0, %1, %2;" : "=l"(d) : "l"(a), "l"(b)); return d;
}
__device__ __forceinline__ void unpack2(ull v, float& lo, float& hi) {
    asm("mov.b64 {%0, %1}, %2;" : "=f"(lo), "=f"(hi) : "l"(v));
}
__device__ __forceinline__ void split_bf16(float v, ushort& h, ushort& l) {
    ushort hb = __bfloat16_as_ushort(__float2bfloat16(v));
    float hf = __uint_as_float(((uint)hb) << 16);
    h = hb;
    l = __bfloat16_as_ushort(__float2bfloat16(v - hf));
}

#define MMA_BF16(D, A0, A1, A2, A3, B0, B1)                                   \
    asm volatile("mma.sync.aligned.m16n8k16.row.col.f32.bf16.bf16.f32 "       \
                 "{%0,%1,%2,%3}, {%4,%5,%6,%7}, {%8,%9}, {%0,%1,%2,%3};"      \
                 : "+f"((D)[0]), "+f"((D)[1]), "+f"((D)[2]), "+f"((D)[3])     \
                 : "r"(A0), "r"(A1), "r"(A2), "r"(A3), "r"(B0), "r"(B1))

// ---------------- scratch (device globals; no allocs allowed) ----------------
__device__ float  g_corr[BB * N1 * N2];          // 32 MB
__device__ ushort g_f1h[BB * N1 * DD];           // [b][n][d] bf16 hi (scaled)
__device__ ushort g_f1l[BB * N1 * DD];
__device__ ushort g_f2h[BB * N2 * DD];
__device__ ushort g_f2l[BB * N2 * DD];
__device__ float4 g_c2p[BB][N2];                 // padded coords2
__device__ float  g_vol [BB * N1 * NCH];         // [b][n][81]
__device__ float  g_h1  [BB * 128 * N1];         // [b][c][n]
__device__ float  g_hmm [BB * N1 * 128];         // [b][n][c: 0..63 max, 64..127 min]
__device__ float  g_W1T [NCH * 128];             // [q][c]
__device__ ushort g_hh[BB * N1 * FC];            // [b][n][192] H bf16 hi
__device__ ushort g_hl[BB * N1 * FC];
__device__ ushort g_wh[FC * FC];                 // [o][192] Wcat bf16 hi
__device__ ushort g_wl[FC * FC];
__device__ double g_volsum[BB][8][2];
__device__ double g_knnmom[BB][14];

// ---------------- prep: zero stats + W1T + Wcat split + coords2 pack ---------
__global__ __launch_bounds__(256) void prep_kernel(const float* __restrict__ W1,
                                                   const float* __restrict__ W2,
                                                   const float* __restrict__ Wo,
                                                   const float* __restrict__ c2) {
    int bid = blockIdx.x;
    int tid = threadIdx.x;
    if (bid < 41) {                                    // W1 transpose -> [q][c]
        int i = bid * 256 + tid;
        if (i < NCH * 128) {
            int q = i >> 7, c = i & 127;
            g_W1T[q * 128 + c] = W1[c * NCH + q];
        }
    } else if (bid < 185) {                            // Wcat split bf16 [o][192]
        int i = (bid - 41) * 256 + tid;
        int o = i / FC, k = i - o * FC;
        float v = (k < 128) ? W2[o * 128 + k] : Wo[o * 64 + (k - 128)];
        ushort h, l; split_bf16(v, h, l);
        g_wh[i] = h; g_wl[i] = l;
    } else if (bid == 185) {                           // zero stat accumulators
        double* vs = &g_volsum[0][0][0];
        double* km = &g_knnmom[0][0];
        if (tid < BB * 8 * 2) vs[tid] = 0.0;
        if (tid < BB * 14)    km[tid] = 0.0;
    } else {                                           // coords2 -> float4
        int b = bid - 186;
        for (int m = tid; m < N2; m += 256) {
            const float* p = c2 + ((size_t)b * N2 + m) * 3;
            g_c2p[b][m] = make_float4(p[0], p[1], p[2], 0.f);
        }
    }
}

// ---------------- fmaps fp32 -> split bf16, transposed [n][d] ----
__global__ __launch_bounds__(256) void cvt_kernel(const float* __restrict__ f1,
                                                  const float* __restrict__ f2) {
    int b = blockIdx.z;
    bool isA = blockIdx.x < 64;
    int ntile = isA ? blockIdx.x : blockIdx.x - 64;
    int dtile = blockIdx.y;
    int NN = isA ? N1 : N2;
    const float* src = isA ? f1 + (size_t)b * DD * N1 : f2 + (size_t)b * DD * N2;
    ushort* dh = isA ? g_f1h + (size_t)b * N1 * DD : g_f2h + (size_t)b * N2 * DD;
    ushort* dl = isA ? g_f1l + (size_t)b * N1 * DD : g_f2l + (size_t)b * N2 * DD;
    float scale = isA ? 0.08838834764831845f : 1.0f;

    __shared__ float tile[32][33];
    int tid = threadIdx.x;
    for (int i = tid; i < 1024; i += 256) {
        int dd = i >> 5, nn = i & 31;
        tile[dd][nn] = src[(size_t)(dtile * 32 + dd) * NN + ntile * 32 + nn];
    }
    __syncthreads();
    for (int i = tid; i < 1024; i += 256) {
        int nn = i >> 5, dd = i & 31;
        float v = tile[dd][nn] * scale;
        ushort hb, lb; split_bf16(v, hb, lb);
        size_t o = (size_t)(ntile * 32 + nn) * DD + dtile * 32 + dd;
        dh[o] = hb;
        dl[o] = lb;
    }
}

// ---------------- corr via split-bf16 mma.sync; tile 128 x 128 ----------
#define CPITCH 40
__global__ __launch_bounds__(256) void corr_kernel() {
    int b  = blockIdx.z;
    int n0 = blockIdx.x * 128;
    int m0 = blockIdx.y * 128;
    __shared__ ushort Ah[128][CPITCH], Al[128][CPITCH];
    __shared__ ushort Bh[128][CPITCH], Bl[128][CPITCH];
    int tid = threadIdx.x, lane = tid & 31, warp = tid >> 5;
    int wm = warp >> 1, wn = warp & 1;
    int g = lane >> 2, t = lane & 3;

    const ushort* f1h = g_f1h + (size_t)b * N1 * DD;
    const ushort* f1l = g_f1l + (size_t)b * N1 * DD;
    const ushort* f2h = g_f2h + (size_t)b * N2 * DD;
    const ushort* f2l = g_f2l + (size_t)b * N2 * DD;

    float d[2][8][4];
#pragma unroll
    for (int i = 0; i < 2; i++)
#pragma unroll
        for (int j = 0; j < 8; j++)
#pragma unroll
            for (int k = 0; k < 4; k++) d[i][j][k] = 0.f;

    for (int kc = 0; kc < 4; kc++) {
        int k0 = kc * 32;
        for (int i = tid; i < 512; i += 256) {
            int r = i >> 2;
            int jj = (i & 3) * 8;
            *(uint4*)&Ah[r][jj] = *(const uint4*)&f1h[(size_t)(n0 + r) * DD + k0 + jj];
            *(uint4*)&Al[r][jj] = *(const uint4*)&f1l[(size_t)(n0 + r) * DD + k0 + jj];
            *(uint4*)&Bh[r][jj] = *(const uint4*)&f2h[(size_t)(m0 + r) * DD + k0 + jj];
            *(uint4*)&Bl[r][jj] = *(const uint4*)&f2l[(size_t)(m0 + r) * DD + k0 + jj];
        }
        __syncthreads();

#pragma unroll
        for (int term = 0; term < 3; term++) {
            const ushort (*Ap)[CPITCH] = (term == 2) ? Al : Ah;
            const ushort (*Bp)[CPITCH] = (term == 1) ? Bl : Bh;
#pragma unroll
            for (int ks = 0; ks < 2; ks++) {
                int sc = 16 * ks + 2 * t;
                uint bf[8][2];
#pragma unroll
                for (int nt = 0; nt < 8; nt++) {
                    int br = wn * 64 + nt * 8 + g;
                    bf[nt][0] = *(const uint*)&Bp[br][sc];
                    bf[nt][1] = *(const uint*)&Bp[br][sc + 8];
                }
#pragma unroll
                for (int mt = 0; mt < 2; mt++) {
                    int ar = wm * 32 + mt * 16 + g;
                    uint a0 = *(const uint*)&Ap[ar][sc];
                    uint a1 = *(const uint*)&Ap[ar + 8][sc];
                    uint a2 = *(const uint*)&Ap[ar][sc + 8];
                    uint a3 = *(const uint*)&Ap[ar + 8][sc + 8];
#pragma unroll
                    for (int nt = 0; nt < 8; nt++)
                        MMA_BF16(d[mt][nt], a0, a1, a2, a3, bf[nt][0], bf[nt][1]);
                }
            }
        }
        __syncthreads();
    }

#pragma unroll
    for (int mt = 0; mt < 2; mt++) {
#pragma unroll
        for (int nt = 0; nt < 8; nt++) {
            int ng = n0 + wm * 32 + mt * 16 + g;
            int mg = m0 + wn * 64 + nt * 8 + 2 * t;
            float2 v0 = make_float2(d[mt][nt][0], d[mt][nt][1]);
            float2 v1 = make_float2(d[mt][nt][2], d[mt][nt][3]);
            *(float2*)&g_corr[((size_t)b * N1 + ng) * N2 + mg] = v0;
            *(float2*)&g_corr[((size_t)b * N1 + ng + 8) * N2 + mg] = v1;
        }
    }
}

// ---------------- row pass: voxel bins + KNN + e-moments + h minmax ---
// __launch_bounds__(256, 6): cap regs ~42 so 6 blocks/SM fit (reg-limited at 48)
__global__ __launch_bounds__(256, 6) void row_kernel(const float* __restrict__ coords,
                           const float* __restrict__ Wk,
                           const float* __restrict__ bk) {
    int b    = blockIdx.y;
    int warp = threadIdx.x >> 5;
    int lane = threadIdx.x & 31;
    int n    = blockIdx.x * 8 + warp;

    __shared__ float4 s_c2[N2];
    __shared__ float sadd[8][NCH];
    __shared__ float scnt[8][NCH];
    __shared__ float smom[14];
    __shared__ float smm[8][128];
    __shared__ float4 sev[8][32];

    if (threadIdx.x < 14) smom[threadIdx.x] = 0.f;
    for (int q = lane; q < NCH; q += 32) { sadd[warp][q] = 0.f; scnt[warp][q] = 0.f; }
    for (int i = threadIdx.x; i < N2; i += 256)
        s_c2[i] = g_c2p[b][i];
    __syncthreads();

    float cx = coords[((size_t)b * N1 + n) * 3 + 0];
    float cy = coords[((size_t)b * N1 + n) * 3 + 1];
    float cz = coords[((size_t)b * N1 + n) * 3 + 2];
    const float* crow = g_corr + ((size_t)b * N1 + n) * N2;

    // ---- binning (nested level guards; bounds checks folded into mx tests)
    float dloc[16];
#pragma unroll 4
    for (int s = 0; s < 16; s++) {
        int m = lane + s * 32;
        float4 c = s_c2[m];
        float qx = c.x - cx;
        float qy = c.y - cy;
        float qz = c.z - cz;
        dloc[s] = qx * qx + qy * qy + qz * qz;
        float mx = fmaxf(fabsf(qx), fmaxf(fabsf(qy), fabsf(qz)));
        if (mx < 1.5f) {
            float cv = crow[m];
            int vx = __float2int_rn(qx);
            int vy = __float2int_rn(qy);
            int vz = __float2int_rn(qz);
            int idx = 54 + vx * 9 + vy * 3 + vz + 13;
            atomicAdd(&sadd[warp][idx], cv);
            atomicAdd(&scnt[warp][idx], 1.f);
            if (mx < 0.75f) {
                vx = __float2int_rn(qx * 2.f);
                vy = __float2int_rn(qy * 2.f);
                vz = __float2int_rn(qz * 2.f);
                idx = 27 + vx * 9 + vy * 3 + vz + 13;
                atomicAdd(&sadd[warp][idx], cv);
                atomicAdd(&scnt[warp][idx], 1.f);
                if (mx < 0.375f) {
                    vx = __float2int_rn(qx * 4.f);
                    vy = __float2int_rn(qy * 4.f);
                    vz = __float2int_rn(qz * 4.f);
                    idx = vx * 9 + vy * 3 + vz + 13;
                    atomicAdd(&sadd[warp][idx], cv);
                    atomicAdd(&scnt[warp][idx], 1.f);
                }
            }
        }
    }

    // ---- top-32 via 4-deep per-lane queue + branchless pop tournament ----
    unsigned consumed = 0;
    unsigned q0d, q0m, q1d, q1m, q2d, q2m, q3d, q3m;
    {
        float bv; int bs;
#define SCAN_MIN(OUTD, OUTM)                                            \
        bv = 3.4e38f; bs = 16;                                          \
        _Pragma("unroll")                                               \
        for (int s = 0; s < 16; s++) {                                  \
            bool ok = !((consumed >> s) & 1u) && (dloc[s] < bv);        \
            if (ok) { bv = dloc[s]; bs = s; }                           \
        }                                                               \
        OUTD = __float_as_uint(bv);                                     \
        OUTM = (unsigned)(lane + bs * 32);                              \
        consumed |= 1u << bs;
        SCAN_MIN(q0d, q0m)
        SCAN_MIN(q1d, q1m)
        SCAN_MIN(q2d, q2m)
        SCAN_MIN(q3d, q3m)
    }
    unsigned selm = 0;
    for (int k = 0; k < KK; k++) {
        unsigned dmin = __reduce_min_sync(0xffffffffu, q0d);
        unsigned mc   = (q0d == dmin) ? q0m : 0xffffffffu;
        unsigned mmin = __reduce_min_sync(0xffffffffu, mc);
        if (lane == k) selm = mmin;
        bool won = (q0d == dmin) && (q0m == mmin);
        q0d = won ? q1d : q0d;  q0m = won ? q1m : q0m;
        q1d = won ? q2d : q1d;  q1m = won ? q2m : q1m;
        q2d = won ? q3d : q2d;  q2m = won ? q3m : q2m;
        q3d = won ? 0xffffffffu : q3d;  q3m = won ? 0xffffffffu : q3m;
        if (__any_sync(0xffffffffu, (q0d == 0xffffffffu) & (consumed != 0xffffu))) {
            if ((q0d == 0xffffffffu) & (consumed != 0xffffu)) {
                float bv = 3.4e38f; int bs = 16;
#pragma unroll
                for (int s = 0; s < 16; s++) {
                    bool ok = !((consumed >> s) & 1u) && (dloc[s] < bv);
                    if (ok) { bv = dloc[s]; bs = s; }
                }
                if (bs < 16) {
                    q0d = __float_as_uint(bv);
                    q0m = (unsigned)(lane + bs * 32);
                    consumed |= 1u << bs;
                }
            }
        }
    }

    int j = (int)selm;
    float e0 = crow[j];
    float4 cj = s_c2[j];
    float e1 = cj.x - cx;
    float e2 = cj.y - cy;
    float e3 = cj.z - cz;
    sev[warp][lane] = make_float4(e0, e1, e2, e3);

    float mv[14] = { e0, e1, e2, e3,
                     e0*e0, e0*e1, e0*e2, e0*e3,
                     e1*e1, e1*e2, e1*e3,
                     e2*e2, e2*e3, e3*e3 };
#pragma unroll
    for (int i = 0; i < 14; i++) {
        float v = mv[i];
#pragma unroll
        for (int off = 16; off; off >>= 1) v += __shfl_xor_sync(0xffffffffu, v, off);
        if (lane == 0) atomicAdd(&smom[i], v);
    }
    __syncwarp();

    // ---- per-channel max/min of raw h over 32 neighbors (smem broadcast) ----
    {
        float4 w0 = ((const float4*)Wk)[lane];
        float4 w1 = ((const float4*)Wk)[lane + 32];
        float bb0 = bk[lane], bb1 = bk[lane + 32];
        float mx0 = -3.4e38f, mn0 = 3.4e38f, mx1 = -3.4e38f, mn1 = 3.4e38f;
#pragma unroll 8
        for (int t = 0; t < 32; t++) {
            float4 e = sev[warp][t];
            float h0 = fmaf(w0.w, e.w, fmaf(w0.z, e.z, fmaf(w0.y, e.y, fmaf(w0.x, e.x, bb0))));
            float h1 = fmaf(w1.w, e.w, fmaf(w1.z, e.z, fmaf(w1.y, e.y, fmaf(w1.x, e.x, bb1))));
            mx0 = fmaxf(mx0, h0); mn0 = fminf(mn0, h0);
            mx1 = fmaxf(mx1, h1); mn1 = fminf(mn1, h1);
        }
        smm[warp][lane]           = mx0;
        smm[warp][lane + 32]      = mx1;
        smm[warp][64 + lane]      = mn0;
        smm[warp][64 + lane + 32] = mn1;
    }

    // voxel features (scatter mean), coalesced row layout [n][81]
    for (int q = lane; q < NCH; q += 32) {
        float cnt = scnt[warp][q];
        g_vol[((size_t)b * N1 + n) * NCH + q] = sadd[warp][q] / fmaxf(cnt, 1.f);
    }
    __syncthreads();
    if (threadIdx.x < 14) atomicAdd(&g_knnmom[b][threadIdx.x], (double)smom[threadIdx.x]);
    int nb = blockIdx.x * 8;
    for (int i = threadIdx.x; i < 8 * 128; i += 256) {
        int r = i >> 7;
        g_hmm[((size_t)b * N1 + nb + r) * 128 + (i & 127)] = smm[r][i & 127];
    }
}

// ---------------- h1 = W1 @ vol + b1, plus GN partial stats (FFMA2) ----------
__global__ __launch_bounds__(256) void h1_kernel(const float* __restrict__ b1) {
    int b  = blockIdx.y;
    int n0 = blockIdx.x * 64;
    int tx = threadIdx.x & 15;
    int ty = threadIdx.x >> 4;
    __shared__ float Ws[27][128];
    __shared__ float Vs[27][64];
    __shared__ float sgs[8], sgss[8];
    if (threadIdx.x < 8) { sgs[threadIdx.x] = 0.f; sgss[threadIdx.x] = 0.f; }

    ull acc2[8][2];
#pragma unroll
    for (int i = 0; i < 8; i++) { acc2[i][0] = 0ull; acc2[i][1] = 0ull; }

    for (int chunk = 0; chunk < 3; chunk++) {
        int q0 = chunk * 27;
        for (int i = threadIdx.x; i < 27 * 128; i += 256) {
            int q = i >> 7, c = i & 127;
            Ws[q][c] = g_W1T[(q0 + q) * 128 + c];
        }
        for (int i = threadIdx.x; i < 27 * 64; i += 256) {
            int nn = i / 27, q = i - nn * 27;
            Vs[q][nn] = g_vol[((size_t)b * N1 + n0 + nn) * NCH + q0 + q];
        }
        __syncthreads();
#pragma unroll
        for (int q = 0; q < 27; q++) {
            float4 a0 = *(const float4*)&Ws[q][ty * 8];
            float4 a1 = *(const float4*)&Ws[q][ty * 8 + 4];
            ulonglong2 bp = *(const ulonglong2*)&Vs[q][tx * 4];
            float av[8] = {a0.x, a0.y, a0.z, a0.w, a1.x, a1.y, a1.z, a1.w};
#pragma unroll
            for (int i = 0; i < 8; i++) {
                ull a2 = pack2(av[i]);
                fma2(acc2[i][0], a2, bp.x);
                fma2(acc2[i][1], a2, bp.y);
            }
        }
        __syncthreads();
    }

    float ls = 0.f, lss = 0.f;
#pragma unroll
    for (int i = 0; i < 8; i++) {
        int c = ty * 8 + i;
        ull b2v = pack2(b1[c]);
        ulonglong2 v;
        v.x = add2(acc2[i][0], b2v);
        v.y = add2(acc2[i][1], b2v);
        *(ulonglong2*)(g_h1 + ((size_t)b * 128 + c) * N1 + n0 + tx * 4) = v;
        float x0, x1, x2, x3;
        unpack2(v.x, x0, x1);
        unpack2(v.y, x2, x3);
        ls  += x0 + x1 + x2 + x3;
        lss += x0 * x0 + x1 * x1 + x2 * x2 + x3 * x3;
    }
    int g = ty >> 1;
    atomicAdd(&sgs[g], ls);
    atomicAdd(&sgss[g], lss);
    __syncthreads();
    if (threadIdx.x < 8) {
        atomicAdd(&g_volsum[b][threadIdx.x][0], (double)sgs[threadIdx.x]);
        atomicAdd(&g_volsum[b][threadIdx.x][1], (double)sgss[threadIdx.x]);
    }
}

// ---------------- hcvt: finalize stats in-block, then H -> bf16 split [n][192]
__global__ __launch_bounds__(256) void hcvt_kernel(const float* __restrict__ g1, const float* __restrict__ be1,
                                                   const float* __restrict__ a1p,
                                                   const float* __restrict__ gk, const float* __restrict__ bek,
                                                   const float* __restrict__ akp,
                                                   const float* __restrict__ Wk, const float* __restrict__ bk) {
    int b  = blockIdx.y;
    int n0 = blockIdx.x * 128;
    float a1 = a1p[0], ak = akp[0];
    __shared__ float sv[64][129];
    __shared__ float s_vstat[8][2];
    __shared__ float s_kstat[8][2];

    if (threadIdx.x < 8) {
        int g = threadIdx.x;
        double cnt = 16.0 * (double)N1;
        double mean = g_volsum[b][g][0] / cnt;
        double var = g_volsum[b][g][1] / cnt - mean * mean;
        s_vstat[g][0] = (float)mean;
        s_vstat[g][1] = (float)(1.0 / sqrt(var + 1e-5));
    } else if (threadIdx.x < 16) {
        int g = threadIdx.x - 8;
        double cnt = (double)N1 * (double)KK;
        double mu[4];
#pragma unroll
        for (int i = 0; i < 4; i++) mu[i] = g_knnmom[b][i] / cnt;
        double S[4][4];
        const int pi[10][2] = {{0,0},{0,1},{0,2},{0,3},{1,1},{1,2},{1,3},{2,2},{2,3},{3,3}};
#pragma unroll
        for (int p = 0; p < 10; p++) {
            double v = g_knnmom[b][4 + p] / cnt;
            S[pi[p][0]][pi[p][1]] = v;
            S[pi[p][1]][pi[p][0]] = v;
        }
        double sm = 0.0, s2 = 0.0;
        for (int c = g * 8; c < g * 8 + 8; c++) {
            double w[4] = { (double)Wk[c*4+0], (double)Wk[c*4+1], (double)Wk[c*4+2], (double)Wk[c*4+3] };
            double bb = (double)bk[c];
            double wm = w[0]*mu[0] + w[1]*mu[1] + w[2]*mu[2] + w[3]*mu[3];
            double q = 0.0;
#pragma unroll
            for (int i = 0; i < 4; i++)
#pragma unroll
                for (int jj = 0; jj < 4; jj++) q += w[i] * S[i][jj] * w[jj];
            double m1 = wm + bb;
            double m2 = q + 2.0 * bb * wm + bb * bb;
            sm += m1; s2 += m2;
        }
        sm *= 0.125; s2 *= 0.125;
        double var = s2 - sm * sm;
        s_kstat[g][0] = (float)sm;
        s_kstat[g][1] = (float)(1.0 / sqrt(var + 1e-5));
    }
    __syncthreads();

    for (int chunk = 0; chunk < 2; chunk++) {
        int c0 = chunk * 64;
        for (int i = threadIdx.x; i < 64 * 128; i += 256) {
            int c = i >> 7, nn = i & 127;
            int k = c0 + c, g = k >> 4;
            float v = g_h1[((size_t)b * 128 + k) * N1 + n0 + nn];
            v = (v - s_vstat[g][0]) * s_vstat[g][1];
            v = v * g1[k] + be1[k];
            sv[c][nn] = (v >= 0.f) ? v : a1 * v;
        }
        __syncthreads();
#pragma unroll
        for (int p = 0; p < 8; p++) {
            int nn = p * 16 + (threadIdx.x >> 4);
            int c4 = (threadIdx.x & 15) * 4;
            ushort4 hh, hl;
            split_bf16(sv[c4 + 0][nn], hh.x, hl.x);
            split_bf16(sv[c4 + 1][nn], hh.y, hl.y);
            split_bf16(sv[c4 + 2][nn], hh.z, hl.z);
            split_bf16(sv[c4 + 3][nn], hh.w, hl.w);
            size_t base = ((size_t)b * N1 + n0 + nn) * FC + c0 + c4;
            *(ushort4*)&g_hh[base] = hh;
            *(ushort4*)&g_hl[base] = hl;
        }
        __syncthreads();
    }
    for (int i = threadIdx.x; i < 128 * 64; i += 256) {
        int nn = i >> 6, c = i & 63;
        int g = c >> 3;
        float slope = s_kstat[g][1] * gk[c];
        const float* hm = g_hmm + ((size_t)b * N1 + n0 + nn) * 128;
        float hsel = (slope >= 0.f) ? hm[c] : hm[64 + c];
        float v = (hsel - s_kstat[g][0]) * slope + bek[c];
        v = (v >= 0.f) ? v : ak * v;
        ushort h, l; split_bf16(v, h, l);
        size_t base = ((size_t)b * N1 + nn + n0) * FC + 128 + c;
        g_hh[base] = h;
        g_hl[base] = l;
    }
}

// ---------------- outmma: out = Wcat @ H + (b2+bo), split-bf16 mma ----------
__global__ __launch_bounds__(256) void outmma_kernel(const float* __restrict__ b2,
                                                     const float* __restrict__ bo,
                                                     float* __restrict__ out) {
    int b  = blockIdx.z;
    int o0 = blockIdx.y * 64;
    int n0 = blockIdx.x * 128;
    __shared__ ushort Ah[64][CPITCH], Al[64][CPITCH];
    __shared__ ushort Bh[128][CPITCH], Bl[128][CPITCH];
    int tid = threadIdx.x, lane = tid & 31, warp = tid >> 5;
    int wm = warp >> 2, wn = warp & 3;
    int g = lane >> 2, t = lane & 3;

    float d[2][4][4];
#pragma unroll
    for (int i = 0; i < 2; i++)
#pragma unroll
        for (int j = 0; j < 4; j++)
#pragma unroll
            for (int k = 0; k < 4; k++) d[i][j][k] = 0.f;

    for (int kc = 0; kc < 6; kc++) {
        int k0 = kc * 32;
        for (int i = tid; i < 256; i += 256) {
            int r = i >> 2, jj = (i & 3) * 8;
            *(uint4*)&Ah[r][jj] = *(const uint4*)&g_wh[(o0 + r) * FC + k0 + jj];
            *(uint4*)&Al[r][jj] = *(const uint4*)&g_wl[(o0 + r) * FC + k0 + jj];
        }
        for (int i = tid; i < 512; i += 256) {
            int r = i >> 2, jj = (i & 3) * 8;
            *(uint4*)&Bh[r][jj] = *(const uint4*)&g_hh[((size_t)b * N1 + n0 + r) * FC + k0 + jj];
            *(uint4*)&Bl[r][jj] = *(const uint4*)&g_hl[((size_t)b * N1 + n0 + r) * FC + k0 + jj];
        }
        __syncthreads();

#pragma unroll
        for (int term = 0; term < 3; term++) {
            const ushort (*Ap)[CPITCH] = (term == 2) ? Al : Ah;
            const ushort (*Bp)[CPITCH] = (term == 1) ? Bl : Bh;
#pragma unroll
            for (int ks = 0; ks < 2; ks++) {
                int sc = 16 * ks + 2 * t;
                uint bf[4][2];
#pragma unroll
                for (int nt = 0; nt < 4; nt++) {
                    int br = wn * 32 + nt * 8 + g;
                    bf[nt][0] = *(const uint*)&Bp[br][sc];
                    bf[nt][1] = *(const uint*)&Bp[br][sc + 8];
                }
#pragma unroll
                for (int mt = 0; mt < 2; mt++) {
                    int ar = wm * 32 + mt * 16 + g;
                    uint a0 = *(const uint*)&Ap[ar][sc];
                    uint a1 = *(const uint*)&Ap[ar + 8][sc];
                    uint a2 = *(const uint*)&Ap[ar][sc + 8];
                    uint a3 = *(const uint*)&Ap[ar + 8][sc + 8];
#pragma unroll
                    for (int nt = 0; nt < 4; nt++)
                        MMA_BF16(d[mt][nt], a0, a1, a2, a3, bf[nt][0], bf[nt][1]);
                }
            }
        }
        __syncthreads();
    }

#pragma unroll
    for (int mt = 0; mt < 2; mt++) {
#pragma unroll
        for (int nt = 0; nt < 4; nt++) {
            int o = o0 + wm * 32 + mt * 16 + g;
            int n = n0 + wn * 32 + nt * 8 + 2 * t;
            float bias0 = b2[o] + bo[o];
            float bias1 = b2[o + 8] + bo[o + 8];
            float2 v0 = make_float2(d[mt][nt][0] + bias0, d[mt][nt][1] + bias0);
            float2 v1 = make_float2(d[mt][nt][2] + bias1, d[mt][nt][3] + bias1);
            *(float2*)&out[((size_t)b * FC + o) * N1 + n] = v0;
            *(float2*)&out[((size_t)b * FC + o + 8) * N1 + n] = v1;
        }
    }
}

// ---------------- launch ----------------
extern "C" void kernel_launch(void* const* d_in, const int* in_sizes, int n_in,
                              void* d_out, int out_size) {
    const float* coords  = (const float*)d_in[0];
    const float* coords2 = (const float*)d_in[1];
    const float* fmap1   = (const float*)d_in[2];
    const float* fmap2   = (const float*)d_in[3];
    const float* W1  = (const float*)d_in[4];
    const float* b1  = (const float*)d_in[5];
    const float* g1  = (const float*)d_in[6];
    const float* be1 = (const float*)d_in[7];
    const float* a1  = (const float*)d_in[8];
    const float* W2  = (const float*)d_in[9];
    const float* b2  = (const float*)d_in[10];
    const float* Wk  = (const float*)d_in[11];
    const float* bk  = (const float*)d_in[12];
    const float* gk  = (const float*)d_in[13];
    const float* bek = (const float*)d_in[14];
    const float* ak  = (const float*)d_in[15];
    const float* Wo  = (const float*)d_in[16];
    const float* bo  = (const float*)d_in[17];
    float* out = (float*)d_out;

    cvt_kernel<<<dim3(80, 4, BB), 256>>>(fmap1, fmap2);                // 0
    corr_kernel<<<dim3(N1 / 128, N2 / 128, BB), 256>>>();              // 1
    prep_kernel<<<194, 256>>>(W1, W2, Wo, coords2);                    // 2
    row_kernel<<<dim3(N1 / 8, BB), 256>>>(coords, Wk, bk);             // 3 (profiled slot)
    h1_kernel<<<dim3(N1 / 64, BB), 256>>>(b1);                         // 4
    hcvt_kernel<<<dim3(N1 / 128, BB), 256>>>(g1, be1, a1, gk, bek, ak, Wk, bk); // 5
    outmma_kernel<<<dim3(N1 / 128, FC / 64, BB), 256>>>(b2, bo, out);  // 6
}

// round 15
// speedup vs baseline: 1.0379x; 1.0081x over previous
#include <cuda_runtime.h>
#include <cuda_bf16.h>
#include <math.h>

#define BB   8
#define N1   2048
#define N2   512
#define DD   128
#define KK   32
#define R3   27
#define NCH  81      // 3*27
#define FC   192

typedef unsigned long long ull;
typedef unsigned int uint;
typedef unsigned short ushort;

// ---- packed f32x2 helpers ----
__device__ __forceinline__ ull pack2(float x) {
    ull r; asm("mov.b64 %0, {%1, %1};" : "=l"(r) : "f"(x)); return r;
}
__device__ __forceinline__ void fma2(ull& d, ull a, ull b) {
    asm("fma.rn.f32x2 %0, %1, %2, %0;" : "+l"(d) : "l"(a), "l"(b));
}
__device__ __forceinline__ void unpack2(ull v, float& lo, float& hi) {
    asm("mov.b64 {%0, %1}, %2;" : "=f"(lo), "=f"(hi) : "l"(v));
}
__device__ __forceinline__ void split_bf16(float v, ushort& h, ushort& l) {
    ushort hb = __bfloat16_as_ushort(__float2bfloat16(v));
    float hf = __uint_as_float(((uint)hb) << 16);
    h = hb;
    l = __bfloat16_as_ushort(__float2bfloat16(v - hf));
}

#define MMA_BF16(D, A0, A1, A2, A3, B0, B1)                                   \
    asm volatile("mma.sync.aligned.m16n8k16.row.col.f32.bf16.bf16.f32 "       \
                 "{%0,%1,%2,%3}, {%4,%5,%6,%7}, {%8,%9}, {%0,%1,%2,%3};"      \
                 : "+f"((D)[0]), "+f"((D)[1]), "+f"((D)[2]), "+f"((D)[3])     \
                 : "r"(A0), "r"(A1), "r"(A2), "r"(A3), "r"(B0), "r"(B1))

// ---------------- scratch (device globals; no allocs allowed) ----------------
__device__ float  g_corr[BB * N1 * N2];          // 32 MB
__device__ ushort g_f1h[BB * N1 * DD];           // [b][n][d] bf16 hi (scaled)
__device__ ushort g_f1l[BB * N1 * DD];
__device__ ushort g_f2h[BB * N2 * DD];
__device__ ushort g_f2l[BB * N2 * DD];
__device__ float4 g_c2p[BB][N2];                 // padded coords2
__device__ float  g_vol [BB * N1 * NCH];         // [b][n][81]
__device__ float  g_h1  [BB * 128 * N1];         // [b][c][n]
__device__ float  g_hmm [BB * N1 * 128];         // [b][n][c: 0..63 max, 64..127 min]
__device__ float  g_W1T [NCH * 128];             // [q][c]
__device__ ushort g_hh[BB * N1 * FC];            // [b][n][192] H bf16 hi
__device__ ushort g_hl[BB * N1 * FC];
__device__ ushort g_wh[FC * FC];                 // [o][192] Wcat bf16 hi
__device__ ushort g_wl[FC * FC];
__device__ double g_volsum[BB][8][2];
__device__ double g_knnmom[BB][14];

// ---------------- cvtprep: fmap split-bf16 transpose + all prep work ---------
// grid (274, 4, BB): x<80 = cvt tiles; x>=80 (y==0, z==0 only) = prep blocks
__global__ __launch_bounds__(256) void cvtprep_kernel(const float* __restrict__ f1,
                                                      const float* __restrict__ f2,
                                                      const float* __restrict__ W1,
                                                      const float* __restrict__ W2,
                                                      const float* __restrict__ Wo,
                                                      const float* __restrict__ c2) {
    int tid = threadIdx.x;
    if (blockIdx.x >= 80) {
        if (blockIdx.y != 0 || blockIdx.z != 0) return;
        int bid = blockIdx.x - 80;                     // 0..193
        if (bid < 41) {                                // W1 transpose -> [q][c]
            int i = bid * 256 + tid;
            if (i < NCH * 128) {
                int q = i >> 7, c = i & 127;
                g_W1T[q * 128 + c] = W1[c * NCH + q];
            }
        } else if (bid < 185) {                        // Wcat split bf16 [o][192]
            int i = (bid - 41) * 256 + tid;
            int o = i / FC, k = i - o * FC;
            float v = (k < 128) ? W2[o * 128 + k] : Wo[o * 64 + (k - 128)];
            ushort h, l; split_bf16(v, h, l);
            g_wh[i] = h; g_wl[i] = l;
        } else if (bid == 185) {                       // zero stat accumulators
            double* vs = &g_volsum[0][0][0];
            double* km = &g_knnmom[0][0];
            if (tid < BB * 8 * 2) vs[tid] = 0.0;
            if (tid < BB * 14)    km[tid] = 0.0;
        } else {                                       // coords2 -> float4
            int b = bid - 186;
            for (int m = tid; m < N2; m += 256) {
                const float* p = c2 + ((size_t)b * N2 + m) * 3;
                g_c2p[b][m] = make_float4(p[0], p[1], p[2], 0.f);
            }
        }
        return;
    }
    // ---- cvt path ----
    int b = blockIdx.z;
    bool isA = blockIdx.x < 64;
    int ntile = isA ? blockIdx.x : blockIdx.x - 64;
    int dtile = blockIdx.y;
    int NN = isA ? N1 : N2;
    const float* src = isA ? f1 + (size_t)b * DD * N1 : f2 + (size_t)b * DD * N2;
    ushort* dh = isA ? g_f1h + (size_t)b * N1 * DD : g_f2h + (size_t)b * N2 * DD;
    ushort* dl = isA ? g_f1l + (size_t)b * N1 * DD : g_f2l + (size_t)b * N2 * DD;
    float scale = isA ? 0.08838834764831845f : 1.0f;

    __shared__ float tile[32][33];
    for (int i = tid; i < 1024; i += 256) {
        int dd = i >> 5, nn = i & 31;
        tile[dd][nn] = src[(size_t)(dtile * 32 + dd) * NN + ntile * 32 + nn];
    }
    __syncthreads();
    for (int i = tid; i < 1024; i += 256) {
        int nn = i >> 5, dd = i & 31;
        float v = tile[dd][nn] * scale;
        ushort hb, lb; split_bf16(v, hb, lb);
        size_t o = (size_t)(ntile * 32 + nn) * DD + dtile * 32 + dd;
        dh[o] = hb;
        dl[o] = lb;
    }
}

// ---------------- corr via split-bf16 mma.sync; tile 128 x 128 ----------
#define CPITCH 40
__global__ __launch_bounds__(256) void corr_kernel() {
    int b  = blockIdx.z;
    int n0 = blockIdx.x * 128;
    int m0 = blockIdx.y * 128;
    __shared__ ushort Ah[128][CPITCH], Al[128][CPITCH];
    __shared__ ushort Bh[128][CPITCH], Bl[128][CPITCH];
    int tid = threadIdx.x, lane = tid & 31, warp = tid >> 5;
    int wm = warp >> 1, wn = warp & 1;
    int g = lane >> 2, t = lane & 3;

    const ushort* f1h = g_f1h + (size_t)b * N1 * DD;
    const ushort* f1l = g_f1l + (size_t)b * N1 * DD;
    const ushort* f2h = g_f2h + (size_t)b * N2 * DD;
    const ushort* f2l = g_f2l + (size_t)b * N2 * DD;

    float d[2][8][4];
#pragma unroll
    for (int i = 0; i < 2; i++)
#pragma unroll
        for (int j = 0; j < 8; j++)
#pragma unroll
            for (int k = 0; k < 4; k++) d[i][j][k] = 0.f;

    for (int kc = 0; kc < 4; kc++) {
        int k0 = kc * 32;
        for (int i = tid; i < 512; i += 256) {
            int r = i >> 2;
            int jj = (i & 3) * 8;
            *(uint4*)&Ah[r][jj] = *(const uint4*)&f1h[(size_t)(n0 + r) * DD + k0 + jj];
            *(uint4*)&Al[r][jj] = *(const uint4*)&f1l[(size_t)(n0 + r) * DD + k0 + jj];
            *(uint4*)&Bh[r][jj] = *(const uint4*)&f2h[(size_t)(m0 + r) * DD + k0 + jj];
            *(uint4*)&Bl[r][jj] = *(const uint4*)&f2l[(size_t)(m0 + r) * DD + k0 + jj];
        }
        __syncthreads();

#pragma unroll
        for (int term = 0; term < 3; term++) {
            const ushort (*Ap)[CPITCH] = (term == 2) ? Al : Ah;
            const ushort (*Bp)[CPITCH] = (term == 1) ? Bl : Bh;
#pragma unroll
            for (int ks = 0; ks < 2; ks++) {
                int sc = 16 * ks + 2 * t;
                uint bf[8][2];
#pragma unroll
                for (int nt = 0; nt < 8; nt++) {
                    int br = wn * 64 + nt * 8 + g;
                    bf[nt][0] = *(const uint*)&Bp[br][sc];
                    bf[nt][1] = *(const uint*)&Bp[br][sc + 8];
                }
#pragma unroll
                for (int mt = 0; mt < 2; mt++) {
                    int ar = wm * 32 + mt * 16 + g;
                    uint a0 = *(const uint*)&Ap[ar][sc];
                    uint a1 = *(const uint*)&Ap[ar + 8][sc];
                    uint a2 = *(const uint*)&Ap[ar][sc + 8];
                    uint a3 = *(const uint*)&Ap[ar + 8][sc + 8];
#pragma unroll
                    for (int nt = 0; nt < 8; nt++)
                        MMA_BF16(d[mt][nt], a0, a1, a2, a3, bf[nt][0], bf[nt][1]);
                }
            }
        }
        __syncthreads();
    }

#pragma unroll
    for (int mt = 0; mt < 2; mt++) {
#pragma unroll
        for (int nt = 0; nt < 8; nt++) {
            int ng = n0 + wm * 32 + mt * 16 + g;
            int mg = m0 + wn * 64 + nt * 8 + 2 * t;
            float2 v0 = make_float2(d[mt][nt][0], d[mt][nt][1]);
            float2 v1 = make_float2(d[mt][nt][2], d[mt][nt][3]);
            *(float2*)&g_corr[((size_t)b * N1 + ng) * N2 + mg] = v0;
            *(float2*)&g_corr[((size_t)b * N1 + ng + 8) * N2 + mg] = v1;
        }
    }
}

// ---------------- row pass: voxel bins + KNN + e-moments + h minmax ---
__global__ __launch_bounds__(256, 6) void row_kernel(const float* __restrict__ coords,
                           const float* __restrict__ Wk,
                           const float* __restrict__ bk) {
    int b    = blockIdx.y;
    int warp = threadIdx.x >> 5;
    int lane = threadIdx.x & 31;
    int n    = blockIdx.x * 8 + warp;

    __shared__ float4 s_c2[N2];
    __shared__ float sadd[8][NCH];
    __shared__ float scnt[8][NCH];
    __shared__ float smom[14];
    __shared__ float smm[8][128];
    __shared__ float4 sev[8][32];

    if (threadIdx.x < 14) smom[threadIdx.x] = 0.f;
    for (int q = lane; q < NCH; q += 32) { sadd[warp][q] = 0.f; scnt[warp][q] = 0.f; }
    for (int i = threadIdx.x; i < N2; i += 256)
        s_c2[i] = g_c2p[b][i];
    __syncthreads();

    float cx = coords[((size_t)b * N1 + n) * 3 + 0];
    float cy = coords[((size_t)b * N1 + n) * 3 + 1];
    float cz = coords[((size_t)b * N1 + n) * 3 + 2];
    const float* crow = g_corr + ((size_t)b * N1 + n) * N2;

    float dloc[16];
#pragma unroll 4
    for (int s = 0; s < 16; s++) {
        int m = lane + s * 32;
        float4 c = s_c2[m];
        float qx = c.x - cx;
        float qy = c.y - cy;
        float qz = c.z - cz;
        dloc[s] = qx * qx + qy * qy + qz * qz;
        float mx = fmaxf(fabsf(qx), fmaxf(fabsf(qy), fabsf(qz)));
        if (mx < 1.5f) {
            float cv = crow[m];
            int vx = __float2int_rn(qx);
            int vy = __float2int_rn(qy);
            int vz = __float2int_rn(qz);
            int idx = 54 + vx * 9 + vy * 3 + vz + 13;
            atomicAdd(&sadd[warp][idx], cv);
            atomicAdd(&scnt[warp][idx], 1.f);
            if (mx < 0.75f) {
                vx = __float2int_rn(qx * 2.f);
                vy = __float2int_rn(qy * 2.f);
                vz = __float2int_rn(qz * 2.f);
                idx = 27 + vx * 9 + vy * 3 + vz + 13;
                atomicAdd(&sadd[warp][idx], cv);
                atomicAdd(&scnt[warp][idx], 1.f);
                if (mx < 0.375f) {
                    vx = __float2int_rn(qx * 4.f);
                    vy = __float2int_rn(qy * 4.f);
                    vz = __float2int_rn(qz * 4.f);
                    idx = vx * 9 + vy * 3 + vz + 13;
                    atomicAdd(&sadd[warp][idx], cv);
                    atomicAdd(&scnt[warp][idx], 1.f);
                }
            }
        }
    }

    // ---- top-32 via 4-deep per-lane queue + branchless pop tournament ----
    unsigned consumed = 0;
    unsigned q0d, q0m, q1d, q1m, q2d, q2m, q3d, q3m;
    {
        float bv; int bs;
#define SCAN_MIN(OUTD, OUTM)                                            \
        bv = 3.4e38f; bs = 16;                                          \
        _Pragma("unroll")                                               \
        for (int s = 0; s < 16; s++) {                                  \
            bool ok = !((consumed >> s) & 1u) && (dloc[s] < bv);        \
            if (ok) { bv = dloc[s]; bs = s; }                           \
        }                                                               \
        OUTD = __float_as_uint(bv);                                     \
        OUTM = (unsigned)(lane + bs * 32);                              \
        consumed |= 1u << bs;
        SCAN_MIN(q0d, q0m)
        SCAN_MIN(q1d, q1m)
        SCAN_MIN(q2d, q2m)
        SCAN_MIN(q3d, q3m)
    }
    unsigned selm = 0;
    for (int k = 0; k < KK; k++) {
        unsigned dmin = __reduce_min_sync(0xffffffffu, q0d);
        unsigned mc   = (q0d == dmin) ? q0m : 0xffffffffu;
        unsigned mmin = __reduce_min_sync(0xffffffffu, mc);
        if (lane == k) selm = mmin;
        bool won = (q0d == dmin) && (q0m == mmin);
        q0d = won ? q1d : q0d;  q0m = won ? q1m : q0m;
        q1d = won ? q2d : q1d;  q1m = won ? q2m : q1m;
        q2d = won ? q3d : q2d;  q2m = won ? q3m : q2m;
        q3d = won ? 0xffffffffu : q3d;  q3m = won ? 0xffffffffu : q3m;
        if (__any_sync(0xffffffffu, (q0d == 0xffffffffu) & (consumed != 0xffffu))) {
            if ((q0d == 0xffffffffu) & (consumed != 0xffffu)) {
                float bv = 3.4e38f; int bs = 16;
#pragma unroll
                for (int s = 0; s < 16; s++) {
                    bool ok = !((consumed >> s) & 1u) && (dloc[s] < bv);
                    if (ok) { bv = dloc[s]; bs = s; }
                }
                if (bs < 16) {
                    q0d = __float_as_uint(bv);
                    q0m = (unsigned)(lane + bs * 32);
                    consumed |= 1u << bs;
                }
            }
        }
    }

    int j = (int)selm;
    float e0 = crow[j];
    float4 cj = s_c2[j];
    float e1 = cj.x - cx;
    float e2 = cj.y - cy;
    float e3 = cj.z - cz;
    sev[warp][lane] = make_float4(e0, e1, e2, e3);

    float mv[14] = { e0, e1, e2, e3,
                     e0*e0, e0*e1, e0*e2, e0*e3,
                     e1*e1, e1*e2, e1*e3,
                     e2*e2, e2*e3, e3*e3 };
#pragma unroll
    for (int i = 0; i < 14; i++) {
        float v = mv[i];
#pragma unroll
        for (int off = 16; off; off >>= 1) v += __shfl_xor_sync(0xffffffffu, v, off);
        if (lane == 0) atomicAdd(&smom[i], v);
    }
    __syncwarp();

    // ---- per-channel max/min of raw h over 32 neighbors (smem broadcast) ----
    {
        float4 w0 = ((const float4*)Wk)[lane];
        float4 w1 = ((const float4*)Wk)[lane + 32];
        float bb0 = bk[lane], bb1 = bk[lane + 32];
        float mx0 = -3.4e38f, mn0 = 3.4e38f, mx1 = -3.4e38f, mn1 = 3.4e38f;
#pragma unroll 8
        for (int t = 0; t < 32; t++) {
            float4 e = sev[warp][t];
            float h0 = fmaf(w0.w, e.w, fmaf(w0.z, e.z, fmaf(w0.y, e.y, fmaf(w0.x, e.x, bb0))));
            float h1 = fmaf(w1.w, e.w, fmaf(w1.z, e.z, fmaf(w1.y, e.y, fmaf(w1.x, e.x, bb1))));
            mx0 = fmaxf(mx0, h0); mn0 = fminf(mn0, h0);
            mx1 = fmaxf(mx1, h1); mn1 = fminf(mn1, h1);
        }
        smm[warp][lane]           = mx0;
        smm[warp][lane + 32]      = mx1;
        smm[warp][64 + lane]      = mn0;
        smm[warp][64 + lane + 32] = mn1;
    }

    // voxel features (scatter mean), coalesced row layout [n][81]
    for (int q = lane; q < NCH; q += 32) {
        float cnt = scnt[warp][q];
        g_vol[((size_t)b * N1 + n) * NCH + q] = sadd[warp][q] / fmaxf(cnt, 1.f);
    }
    __syncthreads();
    if (threadIdx.x < 14) atomicAdd(&g_knnmom[b][threadIdx.x], (double)smom[threadIdx.x]);
    int nb = blockIdx.x * 8;
    for (int i = threadIdx.x; i < 8 * 128; i += 256) {
        int r = i >> 7;
        g_hmm[((size_t)b * N1 + nb + r) * 128 + (i & 127)] = smm[r][i & 127];
    }
}

// ---------------- h1 = W1 @ vol + b1, plus GN partial stats (FFMA2) ----------
// FFMA2 operand roles swapped: weight channel-pairs from LDS (no pack), vol
// values broadcast via pack2 (4 instead of 8 MOVs per q).
__global__ __launch_bounds__(256) void h1_kernel(const float* __restrict__ b1) {
    int b  = blockIdx.y;
    int n0 = blockIdx.x * 64;
    int tx = threadIdx.x & 15;   // n: 4 per thread
    int ty = threadIdx.x >> 4;   // channels: 8 per thread (4 pairs)
    __shared__ float Ws[27][128];
    __shared__ float Vs[27][64];
    __shared__ float sgs[8], sgss[8];
    if (threadIdx.x < 8) { sgs[threadIdx.x] = 0.f; sgss[threadIdx.x] = 0.f; }

    ull acc2[4][4];   // [chpair][n]
#pragma unroll
    for (int i = 0; i < 4; i++)
#pragma unroll
        for (int j = 0; j < 4; j++) acc2[i][j] = 0ull;

    for (int chunk = 0; chunk < 3; chunk++) {
        int q0 = chunk * 27;
        for (int i = threadIdx.x; i < 27 * 128; i += 256) {
            int q = i >> 7, c = i & 127;
            Ws[q][c] = g_W1T[(q0 + q) * 128 + c];
        }
        for (int i = threadIdx.x; i < 27 * 64; i += 256) {
            int nn = i / 27, q = i - nn * 27;
            Vs[q][nn] = g_vol[((size_t)b * N1 + n0 + nn) * NCH + q0 + q];
        }
        __syncthreads();
#pragma unroll
        for (int q = 0; q < 27; q++) {
            ulonglong2 wp01 = *(const ulonglong2*)&Ws[q][ty * 8];       // pairs (c0,c1),(c2,c3)
            ulonglong2 wp23 = *(const ulonglong2*)&Ws[q][ty * 8 + 4];   // pairs (c4,c5),(c6,c7)
            float4 vv = *(const float4*)&Vs[q][tx * 4];
            ull wp[4] = {wp01.x, wp01.y, wp23.x, wp23.y};
            ull vd[4] = {pack2(vv.x), pack2(vv.y), pack2(vv.z), pack2(vv.w)};
#pragma unroll
            for (int p = 0; p < 4; p++)
#pragma unroll
                for (int nn2 = 0; nn2 < 4; nn2++)
                    fma2(acc2[p][nn2], wp[p], vd[nn2]);
        }
        __syncthreads();
    }

    // epilogue: +bias, store per channel, GN partial stats
    float ls = 0.f, lss = 0.f;
#pragma unroll
    for (int p = 0; p < 4; p++) {
        int c0 = ty * 8 + 2 * p;
        float a0[4], a1[4];
#pragma unroll
        for (int nn2 = 0; nn2 < 4; nn2++) unpack2(acc2[p][nn2], a0[nn2], a1[nn2]);
        float bias0 = b1[c0], bias1 = b1[c0 + 1];
        float4 v0, v1;
        v0.x = a0[0] + bias0; v0.y = a0[1] + bias0; v0.z = a0[2] + bias0; v0.w = a0[3] + bias0;
        v1.x = a1[0] + bias1; v1.y = a1[1] + bias1; v1.z = a1[2] + bias1; v1.w = a1[3] + bias1;
        *(float4*)(g_h1 + ((size_t)b * 128 + c0) * N1 + n0 + tx * 4) = v0;
        *(float4*)(g_h1 + ((size_t)b * 128 + c0 + 1) * N1 + n0 + tx * 4) = v1;
        ls  += v0.x + v0.y + v0.z + v0.w + v1.x + v1.y + v1.z + v1.w;
        lss += v0.x * v0.x + v0.y * v0.y + v0.z * v0.z + v0.w * v0.w
             + v1.x * v1.x + v1.y * v1.y + v1.z * v1.z + v1.w * v1.w;
    }
    int g = ty >> 1;
    atomicAdd(&sgs[g], ls);
    atomicAdd(&sgss[g], lss);
    __syncthreads();
    if (threadIdx.x < 8) {
        atomicAdd(&g_volsum[b][threadIdx.x][0], (double)sgs[threadIdx.x]);
        atomicAdd(&g_volsum[b][threadIdx.x][1], (double)sgss[threadIdx.x]);
    }
}

// ---------------- hcvt: finalize stats in-block, then H -> bf16 split [n][192]
__global__ __launch_bounds__(256) void hcvt_kernel(const float* __restrict__ g1, const float* __restrict__ be1,
                                                   const float* __restrict__ a1p,
                                                   const float* __restrict__ gk, const float* __restrict__ bek,
                                                   const float* __restrict__ akp,
                                                   const float* __restrict__ Wk, const float* __restrict__ bk) {
    int b  = blockIdx.y;
    int n0 = blockIdx.x * 128;
    float a1 = a1p[0], ak = akp[0];
    __shared__ float sv[64][129];
    __shared__ float s_vstat[8][2];
    __shared__ float s_kstat[8][2];

    if (threadIdx.x < 8) {
        int g = threadIdx.x;
        double cnt = 16.0 * (double)N1;
        double mean = g_volsum[b][g][0] / cnt;
        double var = g_volsum[b][g][1] / cnt - mean * mean;
        s_vstat[g][0] = (float)mean;
        s_vstat[g][1] = (float)(1.0 / sqrt(var + 1e-5));
    } else if (threadIdx.x < 16) {
        int g = threadIdx.x - 8;
        double cnt = (double)N1 * (double)KK;
        double mu[4];
#pragma unroll
        for (int i = 0; i < 4; i++) mu[i] = g_knnmom[b][i] / cnt;
        double S[4][4];
        const int pi[10][2] = {{0,0},{0,1},{0,2},{0,3},{1,1},{1,2},{1,3},{2,2},{2,3},{3,3}};
#pragma unroll
        for (int p = 0; p < 10; p++) {
            double v = g_knnmom[b][4 + p] / cnt;
            S[pi[p][0]][pi[p][1]] = v;
            S[pi[p][1]][pi[p][0]] = v;
        }
        double sm = 0.0, s2 = 0.0;
        for (int c = g * 8; c < g * 8 + 8; c++) {
            double w[4] = { (double)Wk[c*4+0], (double)Wk[c*4+1], (double)Wk[c*4+2], (double)Wk[c*4+3] };
            double bb = (double)bk[c];
            double wm = w[0]*mu[0] + w[1]*mu[1] + w[2]*mu[2] + w[3]*mu[3];
            double q = 0.0;
#pragma unroll
            for (int i = 0; i < 4; i++)
#pragma unroll
                for (int jj = 0; jj < 4; jj++) q += w[i] * S[i][jj] * w[jj];
            double m1 = wm + bb;
            double m2 = q + 2.0 * bb * wm + bb * bb;
            sm += m1; s2 += m2;
        }
        sm *= 0.125; s2 *= 0.125;
        double var = s2 - sm * sm;
        s_kstat[g][0] = (float)sm;
        s_kstat[g][1] = (float)(1.0 / sqrt(var + 1e-5));
    }
    __syncthreads();

    for (int chunk = 0; chunk < 2; chunk++) {
        int c0 = chunk * 64;
        for (int i = threadIdx.x; i < 64 * 128; i += 256) {
            int c = i >> 7, nn = i & 127;
            int k = c0 + c, g = k >> 4;
            float v = g_h1[((size_t)b * 128 + k) * N1 + n0 + nn];
            v = (v - s_vstat[g][0]) * s_vstat[g][1];
            v = v * g1[k] + be1[k];
            sv[c][nn] = (v >= 0.f) ? v : a1 * v;
        }
        __syncthreads();
#pragma unroll
        for (int p = 0; p < 8; p++) {
            int nn = p * 16 + (threadIdx.x >> 4);
            int c4 = (threadIdx.x & 15) * 4;
            ushort4 hh, hl;
            split_bf16(sv[c4 + 0][nn], hh.x, hl.x);
            split_bf16(sv[c4 + 1][nn], hh.y, hl.y);
            split_bf16(sv[c4 + 2][nn], hh.z, hl.z);
            split_bf16(sv[c4 + 3][nn], hh.w, hl.w);
            size_t base = ((size_t)b * N1 + n0 + nn) * FC + c0 + c4;
            *(ushort4*)&g_hh[base] = hh;
            *(ushort4*)&g_hl[base] = hl;
        }
        __syncthreads();
    }
    for (int i = threadIdx.x; i < 128 * 64; i += 256) {
        int nn = i >> 6, c = i & 63;
        int g = c >> 3;
        float slope = s_kstat[g][1] * gk[c];
        const float* hm = g_hmm + ((size_t)b * N1 + n0 + nn) * 128;
        float hsel = (slope >= 0.f) ? hm[c] : hm[64 + c];
        float v = (hsel - s_kstat[g][0]) * slope + bek[c];
        v = (v >= 0.f) ? v : ak * v;
        ushort h, l; split_bf16(v, h, l);
        size_t base = ((size_t)b * N1 + nn + n0) * FC + 128 + c;
        g_hh[base] = h;
        g_hl[base] = l;
    }
}

// ---------------- outmma: out = Wcat @ H + (b2+bo), split-bf16 mma ----------
__global__ __launch_bounds__(256) void outmma_kernel(const float* __restrict__ b2,
                                                     const float* __restrict__ bo,
                                                     float* __restrict__ out) {
    int b  = blockIdx.z;
    int o0 = blockIdx.y * 64;
    int n0 = blockIdx.x * 128;
    __shared__ ushort Ah[64][CPITCH], Al[64][CPITCH];
    __shared__ ushort Bh[128][CPITCH], Bl[128][CPITCH];
    int tid = threadIdx.x, lane = tid & 31, warp = tid >> 5;
    int wm = warp >> 2, wn = warp & 3;
    int g = lane >> 2, t = lane & 3;

    float d[2][4][4];
#pragma unroll
    for (int i = 0; i < 2; i++)
#pragma unroll
        for (int j = 0; j < 4; j++)
#pragma unroll
            for (int k = 0; k < 4; k++) d[i][j][k] = 0.f;

    for (int kc = 0; kc < 6; kc++) {
        int k0 = kc * 32;
        for (int i = tid; i < 256; i += 256) {
            int r = i >> 2, jj = (i & 3) * 8;
            *(uint4*)&Ah[r][jj] = *(const uint4*)&g_wh[(o0 + r) * FC + k0 + jj];
            *(uint4*)&Al[r][jj] = *(const uint4*)&g_wl[(o0 + r) * FC + k0 + jj];
        }
        for (int i = tid; i < 512; i += 256) {
            int r = i >> 2, jj = (i & 3) * 8;
            *(uint4*)&Bh[r][jj] = *(const uint4*)&g_hh[((size_t)b * N1 + n0 + r) * FC + k0 + jj];
            *(uint4*)&Bl[r][jj] = *(const uint4*)&g_hl[((size_t)b * N1 + n0 + r) * FC + k0 + jj];
        }
        __syncthreads();

#pragma unroll
        for (int term = 0; term < 3; term++) {
            const ushort (*Ap)[CPITCH] = (term == 2) ? Al : Ah;
            const ushort (*Bp)[CPITCH] = (term == 1) ? Bl : Bh;
#pragma unroll
            for (int ks = 0; ks < 2; ks++) {
                int sc = 16 * ks + 2 * t;
                uint bf[4][2];
#pragma unroll
                for (int nt = 0; nt < 4; nt++) {
                    int br = wn * 32 + nt * 8 + g;
                    bf[nt][0] = *(const uint*)&Bp[br][sc];
                    bf[nt][1] = *(const uint*)&Bp[br][sc + 8];
                }
#pragma unroll
                for (int mt = 0; mt < 2; mt++) {
                    int ar = wm * 32 + mt * 16 + g;
                    uint a0 = *(const uint*)&Ap[ar][sc];
                    uint a1 = *(const uint*)&Ap[ar + 8][sc];
                    uint a2 = *(const uint*)&Ap[ar][sc + 8];
                    uint a3 = *(const uint*)&Ap[ar + 8][sc + 8];
#pragma unroll
                    for (int nt = 0; nt < 4; nt++)
                        MMA_BF16(d[mt][nt], a0, a1, a2, a3, bf[nt][0], bf[nt][1]);
                }
            }
        }
        __syncthreads();
    }

#pragma unroll
    for (int mt = 0; mt < 2; mt++) {
#pragma unroll
        for (int nt = 0; nt < 4; nt++) {
            int o = o0 + wm * 32 + mt * 16 + g;
            int n = n0 + wn * 32 + nt * 8 + 2 * t;
            float bias0 = b2[o] + bo[o];
            float bias1 = b2[o + 8] + bo[o + 8];
            float2 v0 = make_float2(d[mt][nt][0] + bias0, d[mt][nt][1] + bias0);
            float2 v1 = make_float2(d[mt][nt][2] + bias1, d[mt][nt][3] + bias1);
            *(float2*)&out[((size_t)b * FC + o) * N1 + n] = v0;
            *(float2*)&out[((size_t)b * FC + o + 8) * N1 + n] = v1;
        }
    }
}

// ---------------- launch ----------------
extern "C" void kernel_launch(void* const* d_in, const int* in_sizes, int n_in,
                              void* d_out, int out_size) {
    const float* coords  = (const float*)d_in[0];
    const float* coords2 = (const float*)d_in[1];
    const float* fmap1   = (const float*)d_in[2];
    const float* fmap2   = (const float*)d_in[3];
    const float* W1  = (const float*)d_in[4];
    const float* b1  = (const float*)d_in[5];
    const float* g1  = (const float*)d_in[6];
    const float* be1 = (const float*)d_in[7];
    const float* a1  = (const float*)d_in[8];
    const float* W2  = (const float*)d_in[9];
    const float* b2  = (const float*)d_in[10];
    const float* Wk  = (const float*)d_in[11];
    const float* bk  = (const float*)d_in[12];
    const float* gk  = (const float*)d_in[13];
    const float* bek = (const float*)d_in[14];
    const float* ak  = (const float*)d_in[15];
    const float* Wo  = (const float*)d_in[16];
    const float* bo  = (const float*)d_in[17];
    float* out = (float*)d_out;

    cvtprep_kernel<<<dim3(274, 4, BB), 256>>>(fmap1, fmap2, W1, W2, Wo, coords2); // 0
    corr_kernel<<<dim3(N1 / 128, N2 / 128, BB), 256>>>();              // 1
    row_kernel<<<dim3(N1 / 8, BB), 256>>>(coords, Wk, bk);             // 2
    h1_kernel<<<dim3(N1 / 64, BB), 256>>>(b1);                         // 3 (profiled slot)
    hcvt_kernel<<<dim3(N1 / 128, BB), 256>>>(g1, be1, a1, gk, bek, ak, Wk, bk); // 4
    outmma_kernel<<<dim3(N1 / 128, FC / 64, BB), 256>>>(b2, bo, out);  // 5
}